// round 4
// baseline (speedup 1.0000x reference)
#include <cuda_runtime.h>
#include <cuda_bf16.h>
#include <cstdint>

// Problem constants
#define BB 8
#define NN 2048
#define DD 1024
#define AA 128

typedef unsigned long long u64;

// Scratch (device globals; no allocation allowed)
__device__ float d_f[BB * NN * AA];                  // 8 MB
__device__ float d_g[BB * NN * AA];                  // 8 MB
__device__ float d_P[(size_t)BB * NN * NN];          // 134 MB raw logits -> normalized probs
__device__ float d_m[BB * NN];                       // row max
__device__ float d_s[BB * NN];                       // row sum of exp

// ---------------------------------------------------------------------------
// Kernel 1: f = x @ Wf + bf ; g = x @ Wg + bg
// x: [B*N, D], Wf/Wg: [D, A]. Block: 64 rows x (128 f + 128 g) cols.
// 256 threads (16x16), micro 4 rows x 8 cols per matrix.
// ---------------------------------------------------------------------------
__global__ __launch_bounds__(256) void k_fg(const float* __restrict__ x,
                                            const float* __restrict__ Wf,
                                            const float* __restrict__ bf,
                                            const float* __restrict__ Wg,
                                            const float* __restrict__ bg) {
    __shared__ float xs[32][65];     // [k][row]
    __shared__ float wfs[32][128];   // [k][col]
    __shared__ float wgs[32][128];

    const int tid = threadIdx.x;
    const int tx = tid & 15;
    const int ty = tid >> 4;
    const int row0 = blockIdx.x * 64;

    float af[4][8];
    float ag[4][8];
#pragma unroll
    for (int i = 0; i < 4; ++i)
#pragma unroll
        for (int j = 0; j < 8; ++j) { af[i][j] = 0.f; ag[i][j] = 0.f; }

    for (int k0 = 0; k0 < DD; k0 += 32) {
        __syncthreads();
        // load x tile transposed: 64 rows x 32 k
#pragma unroll
        for (int u = 0; u < 2; ++u) {
            int f4 = tid + 256 * u;          // 512 float4s
            int r = f4 >> 3, k4 = f4 & 7;
            float4 v = *(const float4*)&x[(size_t)(row0 + r) * DD + k0 + k4 * 4];
            xs[k4 * 4 + 0][r] = v.x;
            xs[k4 * 4 + 1][r] = v.y;
            xs[k4 * 4 + 2][r] = v.z;
            xs[k4 * 4 + 3][r] = v.w;
        }
        // load Wf/Wg chunk: 32 k x 128 cols, row-major
#pragma unroll
        for (int u = 0; u < 4; ++u) {
            int f4 = tid + 256 * u;          // 1024 float4s
            int k = f4 >> 5, c4 = f4 & 31;
            *(float4*)&wfs[k][c4 * 4] = *(const float4*)&Wf[(size_t)(k0 + k) * AA + c4 * 4];
            *(float4*)&wgs[k][c4 * 4] = *(const float4*)&Wg[(size_t)(k0 + k) * AA + c4 * 4];
        }
        __syncthreads();

#pragma unroll 8
        for (int k = 0; k < 32; ++k) {
            float xv[4], wf[8], wg[8];
#pragma unroll
            for (int i = 0; i < 4; ++i) xv[i] = xs[k][ty * 4 + i];
#pragma unroll
            for (int j = 0; j < 8; ++j) {
                wf[j] = wfs[k][tx + 16 * j];
                wg[j] = wgs[k][tx + 16 * j];
            }
#pragma unroll
            for (int i = 0; i < 4; ++i)
#pragma unroll
                for (int j = 0; j < 8; ++j) {
                    af[i][j] += xv[i] * wf[j];
                    ag[i][j] += xv[i] * wg[j];
                }
        }
    }

#pragma unroll
    for (int j = 0; j < 8; ++j) {
        int col = tx + 16 * j;
        float bfv = bf[col];
        float bgv = bg[col];
#pragma unroll
        for (int i = 0; i < 4; ++i) {
            int row = row0 + ty * 4 + i;
            d_f[(size_t)row * AA + col] = af[i][j] + bfv;
            d_g[(size_t)row * AA + col] = ag[i][j] + bgv;
        }
    }
}

// ---------------------------------------------------------------------------
// Kernel 2: raw logits P[b,q,key] = f[b,q,:] . g[b,key,:] and per-row (m, s)
// Block: (batch, 64-query tile). f tile resident (128k x 64q). Keys looped in
// tiles of 128, k chunked by 16. Micro 4q x 8key. Flash-style running max/sum.
// ---------------------------------------------------------------------------
__global__ __launch_bounds__(256) void k_att() {
    __shared__ float fs[128][65];    // [k][q]
    __shared__ float gs[128][17];    // [key][k-chunk]

    const int tid = threadIdx.x;
    const int tx = tid & 15;
    const int ty = tid >> 4;
    const int b = blockIdx.y;
    const int q0 = blockIdx.x * 64;

    // load f tile transposed
#pragma unroll
    for (int u = 0; u < 8; ++u) {
        int f4 = tid + 256 * u;          // 2048 float4s
        int r = f4 >> 5, k4 = f4 & 31;
        float4 v = *(const float4*)&d_f[(size_t)(b * NN + q0 + r) * AA + k4 * 4];
        fs[k4 * 4 + 0][r] = v.x;
        fs[k4 * 4 + 1][r] = v.y;
        fs[k4 * 4 + 2][r] = v.z;
        fs[k4 * 4 + 3][r] = v.w;
    }
    __syncthreads();

    float m[4], s[4];
#pragma unroll
    for (int i = 0; i < 4; ++i) { m[i] = -1e30f; s[i] = 0.f; }

    for (int kt = 0; kt < NN / 128; ++kt) {
        float acc[4][8];
#pragma unroll
        for (int i = 0; i < 4; ++i)
#pragma unroll
            for (int j = 0; j < 8; ++j) acc[i][j] = 0.f;

        for (int kc = 0; kc < 8; ++kc) {
            __syncthreads();
            // load g chunk: 128 keys x 16 k
#pragma unroll
            for (int u = 0; u < 2; ++u) {
                int f4 = tid + 256 * u;      // 512 float4s
                int key = f4 >> 2, k4 = f4 & 3;
                float4 v = *(const float4*)&d_g[(size_t)(b * NN + kt * 128 + key) * AA + kc * 16 + k4 * 4];
                gs[key][k4 * 4 + 0] = v.x;
                gs[key][k4 * 4 + 1] = v.y;
                gs[key][k4 * 4 + 2] = v.z;
                gs[key][k4 * 4 + 3] = v.w;
            }
            __syncthreads();

#pragma unroll
            for (int k = 0; k < 16; ++k) {
                float fv[4], gv[8];
#pragma unroll
                for (int i = 0; i < 4; ++i) fv[i] = fs[kc * 16 + k][ty * 4 + i];
#pragma unroll
                for (int j = 0; j < 8; ++j) gv[j] = gs[tx + 16 * j][k];
#pragma unroll
                for (int i = 0; i < 4; ++i)
#pragma unroll
                    for (int j = 0; j < 8; ++j) acc[i][j] += fv[i] * gv[j];
            }
        }

        // write raw logits + online max/sum update (tile level)
#pragma unroll
        for (int i = 0; i < 4; ++i) {
            int q = q0 + ty * 4 + i;
            float tmax = -1e30f;
#pragma unroll
            for (int j = 0; j < 8; ++j) tmax = fmaxf(tmax, acc[i][j]);
            float nm = fmaxf(m[i], tmax);
            float sum = 0.f;
#pragma unroll
            for (int j = 0; j < 8; ++j) {
                int key = kt * 128 + tx + 16 * j;
                d_P[((size_t)(b * NN + q)) * NN + key] = acc[i][j];
                sum += __expf(acc[i][j] - nm);
            }
            s[i] = s[i] * __expf(m[i] - nm) + sum;
            m[i] = nm;
        }
    }

    // reduce (m, s) across the 16 tx lanes that share each q row (reuse fs)
    __syncthreads();
    float* red = &fs[0][0];   // m at [q*17+t], s at [1088 + q*17+t]
#pragma unroll
    for (int i = 0; i < 4; ++i) {
        int q = ty * 4 + i;
        red[q * 17 + tx] = m[i];
        red[1088 + q * 17 + tx] = s[i];
    }
    __syncthreads();
    if (tid < 64) {
        int q = tid;
        float mm = -1e30f;
#pragma unroll
        for (int t = 0; t < 16; ++t) mm = fmaxf(mm, red[q * 17 + t]);
        float ss = 0.f;
#pragma unroll
        for (int t = 0; t < 16; ++t) ss += red[1088 + q * 17 + t] * __expf(red[q * 17 + t] - mm);
        d_m[b * NN + q0 + q] = mm;
        d_s[b * NN + q0 + q] = ss;
    }
}

// ---------------------------------------------------------------------------
// Kernel 2b: normalize P in place: P = exp(P - m) / s   (one block per row)
// ---------------------------------------------------------------------------
__global__ __launch_bounds__(256) void k_softmax() {
    const int row = blockIdx.x;            // 0 .. B*N-1
    const int tid = threadIdx.x;
    const float m = d_m[row];
    const float inv = 1.0f / d_s[row];
    float4* P4 = (float4*)(d_P + (size_t)row * NN);
#pragma unroll
    for (int u = 0; u < 2; ++u) {
        int idx = tid + 256 * u;           // 512 float4s per row
        float4 v = P4[idx];
        v.x = __expf(v.x - m) * inv;
        v.y = __expf(v.y - m) * inv;
        v.z = __expf(v.z - m) * inv;
        v.w = __expf(v.w - m) * inv;
        P4[idx] = v;
    }
}

// ---------------------------------------------------------------------------
// Kernel 3: out = P @ x + x (per batch GEMM 2048x2048 @ 2048x1024 + residual)
// Block tile 128q x 128d, BK=16, 256 threads, micro 8x8 via packed fma.rn.f32x2.
// Double-buffered shared memory; accumulators held packed in b64 registers.
// ---------------------------------------------------------------------------
__global__ __launch_bounds__(256, 2) void k_out(const float* __restrict__ x,
                                                float* __restrict__ out) {
    __shared__ __align__(16) float Ps[2][16][132];   // [buf][k][q]
    __shared__ __align__(16) float Xs[2][16][132];   // [buf][k][d]

    const int tid = threadIdx.x;
    const int tx = tid & 15;
    const int ty = tid >> 4;
    const int b = blockIdx.z;
    const int q0 = blockIdx.x * 128;
    const int d0 = blockIdx.y * 128;

    const float* Pbase = d_P + ((size_t)(b * NN + q0)) * NN;
    const float* xbase = x + (size_t)b * NN * DD;

    u64 acc[8][4];
#pragma unroll
    for (int i = 0; i < 8; ++i)
#pragma unroll
        for (int j = 0; j < 4; ++j) acc[i][j] = 0ull;

    float4 pReg[2], xReg[2];

    // preload chunk 0
#pragma unroll
    for (int u = 0; u < 2; ++u) {
        int f4 = tid + 256 * u;
        int q = f4 >> 2, k4 = f4 & 3;
        pReg[u] = *(const float4*)&Pbase[(size_t)q * NN + k4 * 4];
    }
#pragma unroll
    for (int u = 0; u < 2; ++u) {
        int f4 = tid + 256 * u;
        int k = f4 >> 5, d4 = f4 & 31;
        xReg[u] = *(const float4*)&xbase[(size_t)k * DD + d0 + d4 * 4];
    }
    // store chunk 0 into buffer 0
#pragma unroll
    for (int u = 0; u < 2; ++u) {
        int f4 = tid + 256 * u;
        int q = f4 >> 2, k4 = f4 & 3;
        Ps[0][k4 * 4 + 0][q] = pReg[u].x;
        Ps[0][k4 * 4 + 1][q] = pReg[u].y;
        Ps[0][k4 * 4 + 2][q] = pReg[u].z;
        Ps[0][k4 * 4 + 3][q] = pReg[u].w;
    }
#pragma unroll
    for (int u = 0; u < 2; ++u) {
        int f4 = tid + 256 * u;
        int k = f4 >> 5, d4 = f4 & 31;
        *(float4*)&Xs[0][k][d4 * 4] = xReg[u];
    }
    __syncthreads();

    for (int t = 0; t < NN / 16; ++t) {
        const int m0n = (t + 1) * 16;
        if (t < NN / 16 - 1) {
            // prefetch next chunk into registers
#pragma unroll
            for (int u = 0; u < 2; ++u) {
                int f4 = tid + 256 * u;
                int q = f4 >> 2, k4 = f4 & 3;
                pReg[u] = *(const float4*)&Pbase[(size_t)q * NN + m0n + k4 * 4];
            }
#pragma unroll
            for (int u = 0; u < 2; ++u) {
                int f4 = tid + 256 * u;
                int k = f4 >> 5, d4 = f4 & 31;
                xReg[u] = *(const float4*)&xbase[(size_t)(m0n + k) * DD + d0 + d4 * 4];
            }
        }

        const int buf = t & 1;
#pragma unroll
        for (int k = 0; k < 16; ++k) {
            const float* psk = &Ps[buf][k][ty * 8];
            const float* xsk = &Xs[buf][k][tx * 2];
            float2 p01 = *(const float2*)(psk + 0);
            float2 p23 = *(const float2*)(psk + 2);
            float2 p45 = *(const float2*)(psk + 4);
            float2 p67 = *(const float2*)(psk + 6);
            u64 xv0 = *(const u64*)(xsk + 0);
            u64 xv1 = *(const u64*)(xsk + 32);
            u64 xv2 = *(const u64*)(xsk + 64);
            u64 xv3 = *(const u64*)(xsk + 96);
            float pq[8] = {p01.x, p01.y, p23.x, p23.y, p45.x, p45.y, p67.x, p67.y};
#pragma unroll
            for (int i = 0; i < 8; ++i) {
                u64 pd;
                asm("mov.b64 %0, {%1, %1};" : "=l"(pd) : "f"(pq[i]));
                asm("fma.rn.f32x2 %0, %1, %2, %0;" : "+l"(acc[i][0]) : "l"(pd), "l"(xv0));
                asm("fma.rn.f32x2 %0, %1, %2, %0;" : "+l"(acc[i][1]) : "l"(pd), "l"(xv1));
                asm("fma.rn.f32x2 %0, %1, %2, %0;" : "+l"(acc[i][2]) : "l"(pd), "l"(xv2));
                asm("fma.rn.f32x2 %0, %1, %2, %0;" : "+l"(acc[i][3]) : "l"(pd), "l"(xv3));
            }
        }

        if (t < NN / 16 - 1) {
            const int nbuf = (t + 1) & 1;
#pragma unroll
            for (int u = 0; u < 2; ++u) {
                int f4 = tid + 256 * u;
                int q = f4 >> 2, k4 = f4 & 3;
                Ps[nbuf][k4 * 4 + 0][q] = pReg[u].x;
                Ps[nbuf][k4 * 4 + 1][q] = pReg[u].y;
                Ps[nbuf][k4 * 4 + 2][q] = pReg[u].z;
                Ps[nbuf][k4 * 4 + 3][q] = pReg[u].w;
            }
#pragma unroll
            for (int u = 0; u < 2; ++u) {
                int f4 = tid + 256 * u;
                int k = f4 >> 5, d4 = f4 & 31;
                *(float4*)&Xs[nbuf][k][d4 * 4] = xReg[u];
            }
            __syncthreads();
        }
    }

    // epilogue: unpack, add residual x, store
#pragma unroll
    for (int i = 0; i < 8; ++i) {
        int q = q0 + ty * 8 + i;
        const float* xr = &x[((size_t)(b * NN + q)) * DD + d0];
        float* outr = &out[((size_t)(b * NN + q)) * DD + d0];
#pragma unroll
        for (int jj = 0; jj < 4; ++jj) {
            int d = tx * 2 + 32 * jj;
            float lo, hi;
            asm("mov.b64 {%0, %1}, %2;" : "=f"(lo), "=f"(hi) : "l"(acc[i][jj]));
            float2 r = *(const float2*)(xr + d);
            float2 o;
            o.x = lo + r.x;
            o.y = hi + r.y;
            *(float2*)(outr + d) = o;
        }
    }
}

// ---------------------------------------------------------------------------
extern "C" void kernel_launch(void* const* d_in, const int* in_sizes, int n_in,
                              void* d_out, int out_size) {
    const float* x  = (const float*)d_in[0];
    const float* Wf = (const float*)d_in[1];
    const float* bf = (const float*)d_in[2];
    const float* Wg = (const float*)d_in[3];
    const float* bg = (const float*)d_in[4];
    float* out = (float*)d_out;

    k_fg<<<BB * NN / 64, 256>>>(x, Wf, bf, Wg, bg);

    dim3 g2(NN / 64, BB);
    k_att<<<g2, 256>>>();

    k_softmax<<<BB * NN, 256>>>();

    dim3 g3(NN / 128, DD / 128, BB);
    k_out<<<g3, 256>>>(x, out);
}

// round 9
// speedup vs baseline: 2.0561x; 2.0561x over previous
#include <cuda_runtime.h>
#include <cuda_fp16.h>
#include <cstdint>

// Problem constants
#define BB 8
#define NN 2048
#define DD 1024
#define AA 128

// Scratch (device globals; no allocation allowed)
__device__ float d_f[BB * NN * AA];                  // 8 MB
__device__ float d_g[BB * NN * AA];                  // 8 MB
__device__ float d_P[(size_t)BB * NN * NN];          // 134 MB raw logits
__device__ float d_m[BB * NN];                       // row max
__device__ float d_s[BB * NN];                       // row sum of exp
__device__ __half d_Ph[(size_t)BB * NN * NN];        // 67 MB softmax probs fp16
__device__ __half d_xTh[(size_t)BB * DD * NN];       // 33.5 MB x^T fp16

__device__ __forceinline__ uint32_t smem_u32(const void* p) {
    uint32_t a;
    asm("{ .reg .u64 t; cvta.to.shared.u64 t, %1; cvt.u32.u64 %0, t; }" : "=r"(a) : "l"(p));
    return a;
}

#define CP_ASYNC16(saddr, gptr) \
    asm volatile("cp.async.cg.shared.global [%0], [%1], 16;" :: "r"(saddr), "l"(gptr) : "memory")
#define CP_COMMIT() asm volatile("cp.async.commit_group;" ::: "memory")

// ---------------------------------------------------------------------------
// Kernel 1: f = x @ Wf + bf ; g = x @ Wg + bg   (fp32 SIMT, unchanged)
// ---------------------------------------------------------------------------
__global__ __launch_bounds__(256) void k_fg(const float* __restrict__ x,
                                            const float* __restrict__ Wf,
                                            const float* __restrict__ bf,
                                            const float* __restrict__ Wg,
                                            const float* __restrict__ bg) {
    __shared__ float xs[32][65];
    __shared__ float wfs[32][128];
    __shared__ float wgs[32][128];

    const int tid = threadIdx.x;
    const int tx = tid & 15;
    const int ty = tid >> 4;
    const int row0 = blockIdx.x * 64;

    float af[4][8], ag[4][8];
#pragma unroll
    for (int i = 0; i < 4; ++i)
#pragma unroll
        for (int j = 0; j < 8; ++j) { af[i][j] = 0.f; ag[i][j] = 0.f; }

    for (int k0 = 0; k0 < DD; k0 += 32) {
        __syncthreads();
#pragma unroll
        for (int u = 0; u < 2; ++u) {
            int f4 = tid + 256 * u;
            int r = f4 >> 3, k4 = f4 & 7;
            float4 v = *(const float4*)&x[(size_t)(row0 + r) * DD + k0 + k4 * 4];
            xs[k4 * 4 + 0][r] = v.x;
            xs[k4 * 4 + 1][r] = v.y;
            xs[k4 * 4 + 2][r] = v.z;
            xs[k4 * 4 + 3][r] = v.w;
        }
#pragma unroll
        for (int u = 0; u < 4; ++u) {
            int f4 = tid + 256 * u;
            int k = f4 >> 5, c4 = f4 & 31;
            *(float4*)&wfs[k][c4 * 4] = *(const float4*)&Wf[(size_t)(k0 + k) * AA + c4 * 4];
            *(float4*)&wgs[k][c4 * 4] = *(const float4*)&Wg[(size_t)(k0 + k) * AA + c4 * 4];
        }
        __syncthreads();

#pragma unroll 8
        for (int k = 0; k < 32; ++k) {
            float xv[4], wf[8], wg[8];
#pragma unroll
            for (int i = 0; i < 4; ++i) xv[i] = xs[k][ty * 4 + i];
#pragma unroll
            for (int j = 0; j < 8; ++j) {
                wf[j] = wfs[k][tx + 16 * j];
                wg[j] = wgs[k][tx + 16 * j];
            }
#pragma unroll
            for (int i = 0; i < 4; ++i)
#pragma unroll
                for (int j = 0; j < 8; ++j) {
                    af[i][j] += xv[i] * wf[j];
                    ag[i][j] += xv[i] * wg[j];
                }
        }
    }

#pragma unroll
    for (int j = 0; j < 8; ++j) {
        int col = tx + 16 * j;
        float bfv = bf[col];
        float bgv = bg[col];
#pragma unroll
        for (int i = 0; i < 4; ++i) {
            int row = row0 + ty * 4 + i;
            d_f[(size_t)row * AA + col] = af[i][j] + bfv;
            d_g[(size_t)row * AA + col] = ag[i][j] + bgv;
        }
    }
}

// ---------------------------------------------------------------------------
// Kernel 2: raw logits + per-row (m, s)   (fp32 SIMT, unchanged)
// ---------------------------------------------------------------------------
__global__ __launch_bounds__(256) void k_att() {
    __shared__ float fs[128][65];
    __shared__ float gs[128][17];

    const int tid = threadIdx.x;
    const int tx = tid & 15;
    const int ty = tid >> 4;
    const int b = blockIdx.y;
    const int q0 = blockIdx.x * 64;

#pragma unroll
    for (int u = 0; u < 8; ++u) {
        int f4 = tid + 256 * u;
        int r = f4 >> 5, k4 = f4 & 31;
        float4 v = *(const float4*)&d_f[(size_t)(b * NN + q0 + r) * AA + k4 * 4];
        fs[k4 * 4 + 0][r] = v.x;
        fs[k4 * 4 + 1][r] = v.y;
        fs[k4 * 4 + 2][r] = v.z;
        fs[k4 * 4 + 3][r] = v.w;
    }
    __syncthreads();

    float m[4], s[4];
#pragma unroll
    for (int i = 0; i < 4; ++i) { m[i] = -1e30f; s[i] = 0.f; }

    for (int kt = 0; kt < NN / 128; ++kt) {
        float acc[4][8];
#pragma unroll
        for (int i = 0; i < 4; ++i)
#pragma unroll
            for (int j = 0; j < 8; ++j) acc[i][j] = 0.f;

        for (int kc = 0; kc < 8; ++kc) {
            __syncthreads();
#pragma unroll
            for (int u = 0; u < 2; ++u) {
                int f4 = tid + 256 * u;
                int key = f4 >> 2, k4 = f4 & 3;
                float4 v = *(const float4*)&d_g[(size_t)(b * NN + kt * 128 + key) * AA + kc * 16 + k4 * 4];
                gs[key][k4 * 4 + 0] = v.x;
                gs[key][k4 * 4 + 1] = v.y;
                gs[key][k4 * 4 + 2] = v.z;
                gs[key][k4 * 4 + 3] = v.w;
            }
            __syncthreads();

#pragma unroll
            for (int k = 0; k < 16; ++k) {
                float fv[4], gv[8];
#pragma unroll
                for (int i = 0; i < 4; ++i) fv[i] = fs[kc * 16 + k][ty * 4 + i];
#pragma unroll
                for (int j = 0; j < 8; ++j) gv[j] = gs[tx + 16 * j][k];
#pragma unroll
                for (int i = 0; i < 4; ++i)
#pragma unroll
                    for (int j = 0; j < 8; ++j) acc[i][j] += fv[i] * gv[j];
            }
        }

#pragma unroll
        for (int i = 0; i < 4; ++i) {
            int q = q0 + ty * 4 + i;
            float tmax = -1e30f;
#pragma unroll
            for (int j = 0; j < 8; ++j) tmax = fmaxf(tmax, acc[i][j]);
            float nm = fmaxf(m[i], tmax);
            float sum = 0.f;
#pragma unroll
            for (int j = 0; j < 8; ++j) {
                int key = kt * 128 + tx + 16 * j;
                d_P[((size_t)(b * NN + q)) * NN + key] = acc[i][j];
                sum += __expf(acc[i][j] - nm);
            }
            s[i] = s[i] * __expf(m[i] - nm) + sum;
            m[i] = nm;
        }
    }

    __syncthreads();
    float* red = &fs[0][0];
#pragma unroll
    for (int i = 0; i < 4; ++i) {
        int q = ty * 4 + i;
        red[q * 17 + tx] = m[i];
        red[1088 + q * 17 + tx] = s[i];
    }
    __syncthreads();
    if (tid < 64) {
        int q = tid;
        float mm = -1e30f;
#pragma unroll
        for (int t = 0; t < 16; ++t) mm = fmaxf(mm, red[q * 17 + t]);
        float ss = 0.f;
#pragma unroll
        for (int t = 0; t < 16; ++t) ss += red[1088 + q * 17 + t] * __expf(red[q * 17 + t] - mm);
        d_m[b * NN + q0 + q] = mm;
        d_s[b * NN + q0 + q] = ss;
    }
}

// ---------------------------------------------------------------------------
// Kernel 2b: softmax -> fp16 probs
// ---------------------------------------------------------------------------
__global__ __launch_bounds__(256) void k_softmax() {
    const int row = blockIdx.x;
    const int tid = threadIdx.x;
    const float m = d_m[row];
    const float inv = 1.0f / d_s[row];
    const float4* P4 = (const float4*)(d_P + (size_t)row * NN);
    __half2* H2 = (__half2*)(d_Ph + (size_t)row * NN);
#pragma unroll
    for (int u = 0; u < 2; ++u) {
        int idx = tid + 256 * u;
        float4 v = P4[idx];
        float p0 = __expf(v.x - m) * inv;
        float p1 = __expf(v.y - m) * inv;
        float p2 = __expf(v.z - m) * inv;
        float p3 = __expf(v.w - m) * inv;
        H2[idx * 2 + 0] = __floats2half2_rn(p0, p1);
        H2[idx * 2 + 1] = __floats2half2_rn(p2, p3);
    }
}

// ---------------------------------------------------------------------------
// Kernel 2c: x^T fp16. xTh[b][d][n] = fp16(x[b][n][d])
// ---------------------------------------------------------------------------
__global__ __launch_bounds__(256) void k_xT(const float* __restrict__ x) {
    __shared__ float t[32][33];
    const int tx = threadIdx.x & 31;
    const int ty = threadIdx.x >> 5;
    const int b = blockIdx.z;
    const int n0 = blockIdx.x * 32;
    const int d0 = blockIdx.y * 32;

#pragma unroll
    for (int k = 0; k < 4; ++k) {
        int nr = ty + 8 * k;
        t[nr][tx] = x[((size_t)(b * NN + n0 + nr)) * DD + d0 + tx];
    }
    __syncthreads();
#pragma unroll
    for (int k = 0; k < 4; ++k) {
        int dr = ty + 8 * k;
        float v = t[tx][dr];
        d_xTh[((size_t)(b * DD + d0 + dr)) * NN + n0 + tx] = __float2half_rn(v);
    }
}

// ---------------------------------------------------------------------------
// Kernel 3: out = P @ x + x via mma.sync fp16 (base-target tensor path)
// CTA 128q x 128d, K-chunk 32, cp.async double buffer, 8 warps (4m x 2n),
// each warp 32x64 = 2x8 m16n8k16 tiles per k16 step.
// ---------------------------------------------------------------------------
#define KCH 32
#define KIT (NN / KCH)                   // 64

__global__ __launch_bounds__(256, 2) void k_out_mma(const float* __restrict__ x,
                                                    float* __restrict__ out) {
    __shared__ __half As[2][128][40];    // rows padded to 80B -> conflict-free ldmatrix
    __shared__ __half Bs[2][128][40];

    const int tid = threadIdx.x;
    const int lane = tid & 31;
    const int wid = tid >> 5;
    const int wm = wid & 3;              // 0..3  -> 32 q-rows each
    const int wn = wid >> 2;             // 0..1  -> 64 d-cols each
    const int b = blockIdx.z;
    const int q0 = blockIdx.y * 128;
    const int d0 = blockIdx.x * 128;

    const __half* Pg = d_Ph + ((size_t)(b * NN + q0)) * NN;
    const __half* Xg = d_xTh + ((size_t)(b * DD + d0)) * NN;

    float c[2][8][4];
#pragma unroll
    for (int mt = 0; mt < 2; ++mt)
#pragma unroll
        for (int nt = 0; nt < 8; ++nt)
#pragma unroll
            for (int r = 0; r < 4; ++r) c[mt][nt][r] = 0.f;

    auto load_stage = [&](int buf, int k0) {
#pragma unroll
        for (int u = 0; u < 2; ++u) {
            int idx = tid + 256 * u;     // 512 segs of 16B per tile
            int row = idx >> 2, seg = idx & 3;
            CP_ASYNC16(smem_u32(&As[buf][row][seg * 8]), Pg + (size_t)row * NN + k0 + seg * 8);
            CP_ASYNC16(smem_u32(&Bs[buf][row][seg * 8]), Xg + (size_t)row * NN + k0 + seg * 8);
        }
        CP_COMMIT();
    };

    load_stage(0, 0);
    load_stage(1, KCH);

#pragma unroll 1
    for (int t = 0; t < KIT; ++t) {
        if (t < KIT - 1) asm volatile("cp.async.wait_group 1;" ::: "memory");
        else             asm volatile("cp.async.wait_group 0;" ::: "memory");
        __syncthreads();

        const int buf = t & 1;
#pragma unroll
        for (int ks = 0; ks < 2; ++ks) {
            // A fragments: two 16x16 m-tiles
            uint32_t a[2][4];
#pragma unroll
            for (int mt = 0; mt < 2; ++mt) {
                uint32_t addr = smem_u32(&As[buf][wm * 32 + mt * 16 + (lane & 15)]
                                            [ks * 16 + (lane >> 4) * 8]);
                asm volatile("ldmatrix.sync.aligned.m8n8.x4.shared.b16 {%0,%1,%2,%3}, [%4];"
                             : "=r"(a[mt][0]), "=r"(a[mt][1]), "=r"(a[mt][2]), "=r"(a[mt][3])
                             : "r"(addr));
            }
            // B fragments: eight n8-tiles (4 ldmatrix.x4, 2 tiles each)
            uint32_t bf[4][4];
#pragma unroll
            for (int bq = 0; bq < 4; ++bq) {
                uint32_t addr = smem_u32(&Bs[buf][wn * 64 + bq * 16 + ((lane >> 4) & 1) * 8 + (lane & 7)]
                                            [ks * 16 + ((lane >> 3) & 1) * 8]);
                asm volatile("ldmatrix.sync.aligned.m8n8.x4.shared.b16 {%0,%1,%2,%3}, [%4];"
                             : "=r"(bf[bq][0]), "=r"(bf[bq][1]), "=r"(bf[bq][2]), "=r"(bf[bq][3])
                             : "r"(addr));
            }
#pragma unroll
            for (int mt = 0; mt < 2; ++mt)
#pragma unroll
                for (int nt = 0; nt < 8; ++nt) {
                    uint32_t b0 = bf[nt >> 1][(nt & 1) * 2 + 0];
                    uint32_t b1 = bf[nt >> 1][(nt & 1) * 2 + 1];
                    asm volatile(
                        "mma.sync.aligned.m16n8k16.row.col.f32.f16.f16.f32 "
                        "{%0,%1,%2,%3}, {%4,%5,%6,%7}, {%8,%9}, {%0,%1,%2,%3};"
                        : "+f"(c[mt][nt][0]), "+f"(c[mt][nt][1]),
                          "+f"(c[mt][nt][2]), "+f"(c[mt][nt][3])
                        : "r"(a[mt][0]), "r"(a[mt][1]), "r"(a[mt][2]), "r"(a[mt][3]),
                          "r"(b0), "r"(b1));
                }
        }

        if (t + 2 < KIT) {
            __syncthreads();
            load_stage(t & 1, (t + 2) * KCH);
        }
    }

    // epilogue: add residual, store fp32
#pragma unroll
    for (int mt = 0; mt < 2; ++mt) {
#pragma unroll
        for (int nt = 0; nt < 8; ++nt) {
            int r0 = q0 + wm * 32 + mt * 16 + (lane >> 2);
            int col = d0 + wn * 64 + nt * 8 + (lane & 3) * 2;
            {
                const float2 xv = *(const float2*)&x[((size_t)(b * NN + r0)) * DD + col];
                float2 ov = {c[mt][nt][0] + xv.x, c[mt][nt][1] + xv.y};
                *(float2*)&out[((size_t)(b * NN + r0)) * DD + col] = ov;
            }
            {
                int r1 = r0 + 8;
                const float2 xv = *(const float2*)&x[((size_t)(b * NN + r1)) * DD + col];
                float2 ov = {c[mt][nt][2] + xv.x, c[mt][nt][3] + xv.y};
                *(float2*)&out[((size_t)(b * NN + r1)) * DD + col] = ov;
            }
        }
    }
}

// ---------------------------------------------------------------------------
extern "C" void kernel_launch(void* const* d_in, const int* in_sizes, int n_in,
                              void* d_out, int out_size) {
    const float* x  = (const float*)d_in[0];
    const float* Wf = (const float*)d_in[1];
    const float* bf = (const float*)d_in[2];
    const float* Wg = (const float*)d_in[3];
    const float* bg = (const float*)d_in[4];
    float* out = (float*)d_out;

    k_fg<<<BB * NN / 64, 256>>>(x, Wf, bf, Wg, bg);

    dim3 gsx(NN / 32, DD / 32, BB);
    k_xT<<<gsx, 256>>>(x);

    dim3 g2(NN / 64, BB);
    k_att<<<g2, 256>>>();

    k_softmax<<<BB * NN, 256>>>();

    dim3 g3(DD / 128, NN / 128, BB);     // d-tile fastest -> P rows reused in L2
    k_out_mma<<<g3, 256>>>(x, out);
}